// round 1
// baseline (speedup 1.0000x reference)
#include <cuda_runtime.h>
#include <cstdint>

// 3x3 erosion + dilation, fp32, NCHW (8,32,512,512), replicate border
// == min/max over valid in-bounds 3x3 window (pad with +inf / -inf).
//
// Strategy: separable. Each block owns one full 512-wide row segment
// (128 threads x float4) and slides vertically over a 32-row strip,
// keeping the horizontal 3-min/3-max of three rows in registers.
// Each input element is read once per strip (+2 halo rows / strip).
// Purely HBM-bound: ~768 MB total traffic.

#define NC     256      // N*C = 8*32
#define H      512
#define W      512
#define ROWS   32       // rows per block strip
#define THREADS 128     // 128 * 4 floats = 512 = W

#define POS_INF __int_as_float(0x7f800000)
#define NEG_INF __int_as_float(0xff800000)

struct RowMM {
    float4 mn;
    float4 mx;
};

// Load row y of one plane, compute horizontal 3-window min/max for this
// thread's 4 output columns. Out-of-bounds horizontal neighbors use the
// identity (inf for min, -inf for max).
__device__ __forceinline__ RowMM load_row_hmm(const float* __restrict__ p,
                                              int y, int xbase) {
    RowMM r;
    const float4 v = *reinterpret_cast<const float4*>(p + (size_t)y * W + xbase);

    float lmn = POS_INF, lmx = NEG_INF;
    float rmn = POS_INF, rmx = NEG_INF;
    if (xbase > 0) {
        float l = p[(size_t)y * W + xbase - 1];   // neighbor's lane; L1 hit
        lmn = l; lmx = l;
    }
    if (xbase + 4 < W) {
        float rr = p[(size_t)y * W + xbase + 4];  // neighbor's lane; L1 hit
        rmn = rr; rmx = rr;
    }

    r.mn.x = fminf(lmn, fminf(v.x, v.y));
    r.mn.y = fminf(v.x, fminf(v.y, v.z));
    r.mn.z = fminf(v.y, fminf(v.z, v.w));
    r.mn.w = fminf(v.z, fminf(v.w, rmn));

    r.mx.x = fmaxf(lmx, fmaxf(v.x, v.y));
    r.mx.y = fmaxf(v.x, fmaxf(v.y, v.z));
    r.mx.z = fmaxf(v.y, fmaxf(v.z, v.w));
    r.mx.w = fmaxf(v.z, fmaxf(v.w, rmx));
    return r;
}

__device__ __forceinline__ RowMM identity_row() {
    RowMM r;
    r.mn.x = r.mn.y = r.mn.z = r.mn.w = POS_INF;
    r.mx.x = r.mx.y = r.mx.z = r.mx.w = NEG_INF;
    return r;
}

__global__ void __launch_bounds__(THREADS)
morph3x3_kernel(const float* __restrict__ x,
                float* __restrict__ dil,
                float* __restrict__ ero) {
    const int plane = blockIdx.y;          // 0..NC-1
    const int strip = blockIdx.x;          // 0..H/ROWS-1
    const int y0    = strip * ROWS;
    const int xbase = threadIdx.x * 4;

    const float* p  = x   + (size_t)plane * H * W;
    float*       pd = dil + (size_t)plane * H * W;
    float*       pe = ero + (size_t)plane * H * W;

    // prev = row y0-1, cur = row y0
    RowMM prev = (y0 == 0) ? identity_row() : load_row_hmm(p, y0 - 1, xbase);
    RowMM cur  = load_row_hmm(p, y0, xbase);

    #pragma unroll 4
    for (int iy = 0; iy < ROWS; ++iy) {
        const int y  = y0 + iy;
        const int yn = y + 1;
        RowMM next = (yn < H) ? load_row_hmm(p, yn, xbase) : identity_row();

        float4 omn, omx;
        omn.x = fminf(prev.mn.x, fminf(cur.mn.x, next.mn.x));
        omn.y = fminf(prev.mn.y, fminf(cur.mn.y, next.mn.y));
        omn.z = fminf(prev.mn.z, fminf(cur.mn.z, next.mn.z));
        omn.w = fminf(prev.mn.w, fminf(cur.mn.w, next.mn.w));

        omx.x = fmaxf(prev.mx.x, fmaxf(cur.mx.x, next.mx.x));
        omx.y = fmaxf(prev.mx.y, fmaxf(cur.mx.y, next.mx.y));
        omx.z = fmaxf(prev.mx.z, fmaxf(cur.mx.z, next.mx.z));
        omx.w = fmaxf(prev.mx.w, fmaxf(cur.mx.w, next.mx.w));

        *reinterpret_cast<float4*>(pd + (size_t)y * W + xbase) = omx;  // dilated = max
        *reinterpret_cast<float4*>(pe + (size_t)y * W + xbase) = omn;  // eroded  = min

        prev = cur;
        cur  = next;
    }
}

extern "C" void kernel_launch(void* const* d_in, const int* in_sizes, int n_in,
                              void* d_out, int out_size) {
    const float* x = (const float*)d_in[0];
    float* out = (float*)d_out;

    const size_t plane_elems = (size_t)NC * H * W;   // 67,108,864
    float* dil = out;                 // tuple order: (dilated, eroded)
    float* ero = out + plane_elems;

    dim3 grid(H / ROWS, NC);   // (16, 256)
    dim3 block(THREADS);
    morph3x3_kernel<<<grid, block>>>(x, dil, ero);
}

// round 3
// speedup vs baseline: 1.0326x; 1.0326x over previous
#include <cuda_runtime.h>
#include <cstdint>

// 3x3 erosion + dilation, fp32, NCHW (8,32,512,512), replicate border.
// Separable: horizontal 3-min/max via warp shuffles (one LDG.128 per row
// per thread), vertical 3-reduce over register-resident rows.
// Two rows processed per loop iteration for 2x memory-level parallelism.

#define NC      256      // N*C
#define H       512
#define W       512
#define ROWS    32       // rows per block strip
#define THREADS 128      // 128 * 4 floats = 512 = W

#define POS_INF __int_as_float(0x7f800000)
#define NEG_INF __int_as_float(0xff800000)

struct RowMM {
    float4 mn;
    float4 mx;
};

// Horizontal 3-window min/max from an already-loaded float4.
// Neighbors come from warp shuffles; warp-seam lanes (0/31) fetch one
// scalar from global (L1 hit on the adjacent warp's line).
__device__ __forceinline__ RowMM hmm_from(float4 v, const float* __restrict__ row,
                                          int xbase, int lane) {
    float l = __shfl_up_sync(0xffffffffu, v.w, 1);
    float r = __shfl_down_sync(0xffffffffu, v.x, 1);
    if (lane == 0 && xbase > 0)      l = row[xbase - 1];
    if (lane == 31 && xbase + 4 < W) r = row[xbase + 4];

    const bool lv = (xbase > 0);       // false only for the leftmost thread
    const bool rv = (xbase + 4 < W);   // false only for the rightmost thread
    const float lmn = lv ? l : POS_INF;
    const float lmx = lv ? l : NEG_INF;
    const float rmn = rv ? r : POS_INF;
    const float rmx = rv ? r : NEG_INF;

    RowMM o;
    o.mn.x = fminf(lmn, fminf(v.x, v.y));
    o.mn.y = fminf(v.x, fminf(v.y, v.z));
    o.mn.z = fminf(v.y, fminf(v.z, v.w));
    o.mn.w = fminf(v.z, fminf(v.w, rmn));

    o.mx.x = fmaxf(lmx, fmaxf(v.x, v.y));
    o.mx.y = fmaxf(v.x, fmaxf(v.y, v.z));
    o.mx.z = fmaxf(v.y, fmaxf(v.z, v.w));
    o.mx.w = fmaxf(v.z, fmaxf(v.w, rmx));
    return o;
}

__device__ __forceinline__ RowMM identity_row() {
    RowMM r;
    r.mn.x = r.mn.y = r.mn.z = r.mn.w = POS_INF;
    r.mx.x = r.mx.y = r.mx.z = r.mx.w = NEG_INF;
    return r;
}

__device__ __forceinline__ void vmerge_store(const RowMM& a, const RowMM& b,
                                             const RowMM& c,
                                             float* __restrict__ pd,
                                             float* __restrict__ pe,
                                             size_t off) {
    float4 omn, omx;
    omn.x = fminf(a.mn.x, fminf(b.mn.x, c.mn.x));
    omn.y = fminf(a.mn.y, fminf(b.mn.y, c.mn.y));
    omn.z = fminf(a.mn.z, fminf(b.mn.z, c.mn.z));
    omn.w = fminf(a.mn.w, fminf(b.mn.w, c.mn.w));

    omx.x = fmaxf(a.mx.x, fmaxf(b.mx.x, c.mx.x));
    omx.y = fmaxf(a.mx.y, fmaxf(b.mx.y, c.mx.y));
    omx.z = fmaxf(a.mx.z, fmaxf(b.mx.z, c.mx.z));
    omx.w = fmaxf(a.mx.w, fmaxf(b.mx.w, c.mx.w));

    __stcs(reinterpret_cast<float4*>(pd + off), omx);  // dilated = max
    __stcs(reinterpret_cast<float4*>(pe + off), omn);  // eroded  = min
}

__global__ void __launch_bounds__(THREADS)
morph3x3_kernel(const float* __restrict__ x,
                float* __restrict__ dil,
                float* __restrict__ ero) {
    const int plane = blockIdx.y;
    const int strip = blockIdx.x;
    const int y0    = strip * ROWS;
    const int xbase = threadIdx.x * 4;
    const int lane  = threadIdx.x & 31;

    const float* p  = x   + (size_t)plane * H * W;
    float*       pd = dil + (size_t)plane * H * W;
    float*       pe = ero + (size_t)plane * H * W;

    RowMM prev, cur;
    {
        // prev = row y0-1 (or identity at top edge), cur = row y0.
        const int ym = (y0 == 0) ? 0 : (y0 - 1);
        const float* rm = p + (size_t)ym * W;
        const float* rc = p + (size_t)y0 * W;
        const float4 vm = *reinterpret_cast<const float4*>(rm + xbase);
        const float4 vc = *reinterpret_cast<const float4*>(rc + xbase);
        prev = hmm_from(vm, rm, xbase, lane);
        cur  = hmm_from(vc, rc, xbase, lane);
        if (y0 == 0) prev = identity_row();
    }

    #pragma unroll 2
    for (int iy = 0; iy < ROWS; iy += 2) {
        const int y = y0 + iy;
        // Row y+1 is always in range inside the loop (iy <= ROWS-2).
        const float* r1 = p + (size_t)(y + 1) * W;
        const int y2 = (y + 2 < H) ? (y + 2) : (H - 1);   // clamped; fixed up below
        const float* r2 = p + (size_t)y2 * W;

        // Issue both row loads back-to-back (independent -> 2x MLP).
        const float4 v1 = *reinterpret_cast<const float4*>(r1 + xbase);
        const float4 v2 = *reinterpret_cast<const float4*>(r2 + xbase);

        RowMM n1 = hmm_from(v1, r1, xbase, lane);
        RowMM n2 = hmm_from(v2, r2, xbase, lane);
        if (y + 2 >= H) n2 = identity_row();

        const size_t o0 = (size_t)y * W + xbase;
        vmerge_store(prev, cur, n1, pd, pe, o0);       // output row y
        vmerge_store(cur, n1, n2, pd, pe, o0 + W);     // output row y+1

        prev = n1;
        cur  = n2;
    }
}

extern "C" void kernel_launch(void* const* d_in, const int* in_sizes, int n_in,
                              void* d_out, int out_size) {
    const float* x = (const float*)d_in[0];
    float* out = (float*)d_out;

    const size_t plane_elems = (size_t)NC * H * W;
    float* dil = out;                 // tuple order: (dilated, eroded)
    float* ero = out + plane_elems;

    dim3 grid(H / ROWS, NC);   // (16, 256)
    dim3 block(THREADS);
    morph3x3_kernel<<<grid, block>>>(x, dil, ero);
}